// round 16
// baseline (speedup 1.0000x reference)
#include <cuda_runtime.h>

// ForwardKinematicsLayer — SMPL 24-joint FK, batch = 262144.
//
// Inputs (metadata order):
//   d_in[0] local_rots : f32 [B, 24, 3, 3]   (B*216 elements)
//   d_in[1] root_pos   : f32 [B, 3]
//   d_in[2] offsets    : f32 [24, 3]
// Output:
//   d_out[0 .. B*72)        global_pos : f32 [B, 24, 3]
//   d_out[B*72 .. B*288)    global_rots: f32 [B, 24, 3, 3]
//
// R15 design = R11 winner (ITEMS=32 tile, odd smem strides 217/73,
// one-thread-per-item register-resident FK chain, 2 barriers) with a SIXTH
// phase machine per SM: TPB=96, __launch_bounds__(96,6).
//   smem 37,120 B/CTA x 6 = 222.7 KB/SM; reg cap 65536/576 = 113 >= the 96
//   this code compiles to -> no spills. 18 warps/SM (vs 20) but 6
//   independently-phased CTAs (vs 5) decorrelate compute/barrier windows
//   against the DRAM read stream. No cache hints, no prefetch (R15 showed
//   both neutral-to-negative).

#define NJ     24
#define TPB    96
#define ITEMS  32
#define RPAD   217                  // 216 rot floats + 1 pad (odd word stride)
#define PPAD   73                   // 72 pos floats + 1 pad (odd word stride)

static __device__ __forceinline__ int par_of(int j) {
    constexpr int kPar[NJ] = {-1, 0, 0, 0, 1, 2, 3, 4, 5, 6, 7, 8,
                               9, 9, 9, 12, 13, 14, 16, 17, 18, 19, 20, 21};
    return kPar[j];
}

__global__ void __launch_bounds__(TPB, 6)
fk_kernel(const float* __restrict__ lrots,   // [B,24,3,3]
          const float* __restrict__ rootp,   // [B,3]
          const float* __restrict__ offs,    // [24,3]
          float* __restrict__ out,           // [B*72 pos | B*216 rot]
          int batch)
{
    extern __shared__ float sm[];            // rot: ITEMS*RPAD | pos: ITEMS*PPAD
    float* rsm = sm;
    float* psm = sm + ITEMS * RPAD;
    __shared__ float soffs[NJ * 3];

    const int tid = threadIdx.x;
    const long long base_item = (long long)blockIdx.x * ITEMS;

    if (tid < NJ * 3) soffs[tid] = offs[tid];   // 72 < TPB=96: single fill OK

    const float* in_rot  = lrots + base_item * 216;
    float*       out_pos = out;
    float*       out_rot = out + (long long)batch * 72;

    // ------- Phase 1: coalesced gmem -> smem (local rots + root pos) -------
    // 32*216/96 = 72 fully-unrolled iterations => deep LDG MLP per warp.
#pragma unroll
    for (int k = 0; k < (ITEMS * 216) / TPB; ++k) {
        int idx  = k * TPB + tid;
        int item = idx / 216;
        int e    = idx - item * 216;
        rsm[item * RPAD + e] = in_rot[idx];
    }
    {   // root positions -> pos smem rows [item*PPAD + 0..2]
        // ITEMS*3 = 96 == TPB: every thread stages exactly one word.
        const float* rp = rootp + base_item * 3;
        int item = tid / 3;
        int c    = tid - item * 3;
        psm[item * PPAD + c] = rp[tid];
    }
    __syncthreads();

    // ------- Phase 2: FK chain, threads 0..31, parents in registers --------
    if (tid < ITEMS) {
        float* my = rsm + tid * RPAD;        // this item's 24 rot slots
        float* mp = psm + tid * PPAD;        // this item's 24 pos slots

        float G[NJ][9];                      // SSA'd by full unroll; ~3 live
        float P[NJ][3];

#pragma unroll
        for (int c = 0; c < 9; ++c) G[0][c] = my[c];    // joint 0: G == L
#pragma unroll
        for (int c = 0; c < 3; ++c) P[0][c] = mp[c];    // root pos (staged)

#pragma unroll
        for (int j = 1; j < NJ; ++j) {
            const int p = par_of(j);

            float L[9];
#pragma unroll
            for (int c = 0; c < 9; ++c) L[c] = my[j * 9 + c];

            const float o0 = soffs[j * 3 + 0];
            const float o1 = soffs[j * 3 + 1];
            const float o2 = soffs[j * 3 + 2];

#pragma unroll
            for (int i = 0; i < 3; ++i) {
                P[j][i] = P[p][i]
                        + G[p][i * 3 + 0] * o0
                        + G[p][i * 3 + 1] * o1
                        + G[p][i * 3 + 2] * o2;
                mp[j * 3 + i] = P[j][i];     // stage pos immediately
            }
#pragma unroll
            for (int i = 0; i < 3; ++i) {
#pragma unroll
                for (int c = 0; c < 3; ++c) {
                    float g = G[p][i * 3 + 0] * L[0 * 3 + c]
                            + G[p][i * 3 + 1] * L[1 * 3 + c]
                            + G[p][i * 3 + 2] * L[2 * 3 + c];
                    G[j][i * 3 + c] = g;
                    my[j * 9 + i * 3 + c] = g;   // stage global rot in place
                }
            }
        }
    }
    __syncthreads();

    // ------- Phase 3: coalesced smem -> gmem (global rots, then pos) -------
    {
        const long long rot_base = base_item * 216;
#pragma unroll
        for (int k = 0; k < (ITEMS * 216) / TPB; ++k) {   // 72 iterations
            int idx  = k * TPB + tid;
            int item = idx / 216;
            int e    = idx - item * 216;
            out_rot[rot_base + idx] = rsm[item * RPAD + e];
        }
        const long long pos_base = base_item * 72;
#pragma unroll
        for (int k = 0; k < (ITEMS * 72) / TPB; ++k) {    // 24 iterations
            int idx  = k * TPB + tid;
            int item = idx / 72;
            int e    = idx - item * 72;
            out_pos[pos_base + idx] = psm[item * PPAD + e];
        }
    }
}

extern "C" void kernel_launch(void* const* d_in, const int* in_sizes, int n_in,
                              void* d_out, int out_size)
{
    const float* lrots = (const float*)d_in[0];
    const float* rootp = (const float*)d_in[1];
    const float* offs  = (const float*)d_in[2];
    float*       out   = (float*)d_out;

    const int batch = in_sizes[0] / 216;                 // 262144
    const int grid  = batch / ITEMS;                     // 8192 blocks
    const int smem  = (ITEMS * RPAD + ITEMS * PPAD) * (int)sizeof(float); // 37,120 B

    cudaFuncSetAttribute(fk_kernel,
                         cudaFuncAttributeMaxDynamicSharedMemorySize, smem);

    fk_kernel<<<grid, TPB, smem>>>(lrots, rootp, offs, out, batch);
}

// round 17
// speedup vs baseline: 1.0050x; 1.0050x over previous
#include <cuda_runtime.h>

// ForwardKinematicsLayer — SMPL 24-joint FK, batch = 262144.
//
// Inputs (metadata order):
//   d_in[0] local_rots : f32 [B, 24, 3, 3]   (B*216 elements)
//   d_in[1] root_pos   : f32 [B, 3]
//   d_in[2] offsets    : f32 [24, 3]
// Output:
//   d_out[0 .. B*72)        global_pos : f32 [B, 24, 3]
//   d_out[B*72 .. B*288)    global_rots: f32 [B, 24, 3, 3]
//
// R16 design = R11 winner (TPB=128, ITEMS=32 tile, odd smem strides
// 217/73, register-resident rot chain, 2 barriers) pushed to SIX CTAs/SM
// (24 warps/SM): __launch_bounds__(128, 6).
//   - Evidence: perf tracks total warps/SM (R11 20w=84.9, R16 18w=102.9,
//     R5 8w=260) — DRAM saturation is warp-count-limited. 6 CTAs of the
//     SAME tile adds +20% outstanding loads without lengthening phases.
//   - Register fit: 65536/768 = 85 regs/thread. To avoid spills, the
//     position chain no longer keeps P[NJ][3] in registers: parent
//     positions are RE-READ from the pos-smem staging buffer (written
//     earlier by the same thread; stride 73 odd -> conflict-free). The
//     rotation chain — the critical path — stays fully register-resident.

#define NJ     24
#define TPB    128
#define ITEMS  32
#define RPAD   217                  // 216 rot floats + 1 pad (odd word stride)
#define PPAD   73                   // 72 pos floats + 1 pad (odd word stride)

static __device__ __forceinline__ int par_of(int j) {
    constexpr int kPar[NJ] = {-1, 0, 0, 0, 1, 2, 3, 4, 5, 6, 7, 8,
                               9, 9, 9, 12, 13, 14, 16, 17, 18, 19, 20, 21};
    return kPar[j];
}

__global__ void __launch_bounds__(TPB, 6)
fk_kernel(const float* __restrict__ lrots,   // [B,24,3,3]
          const float* __restrict__ rootp,   // [B,3]
          const float* __restrict__ offs,    // [24,3]
          float* __restrict__ out,           // [B*72 pos | B*216 rot]
          int batch)
{
    extern __shared__ float sm[];            // rot: ITEMS*RPAD | pos: ITEMS*PPAD
    float* rsm = sm;
    float* psm = sm + ITEMS * RPAD;
    __shared__ float soffs[NJ * 3];

    const int tid = threadIdx.x;
    const long long base_item = (long long)blockIdx.x * ITEMS;

    if (tid < NJ * 3) soffs[tid] = offs[tid];   // 72 < TPB=128: single fill OK

    const float* in_rot  = lrots + base_item * 216;
    float*       out_pos = out;
    float*       out_rot = out + (long long)batch * 72;

    // ------- Phase 1: coalesced gmem -> smem (local rots + root pos) -------
    // 32*216/128 = 54 fully-unrolled iterations => deep LDG MLP per warp.
#pragma unroll
    for (int k = 0; k < (ITEMS * 216) / TPB; ++k) {
        int idx  = k * TPB + tid;
        int item = idx / 216;
        int e    = idx - item * 216;
        rsm[item * RPAD + e] = in_rot[idx];
    }
    {   // root positions -> pos smem rows [item*PPAD + 0..2]  (96 words < TPB)
        const float* rp = rootp + base_item * 3;
        if (tid < ITEMS * 3) {
            int item = tid / 3;
            int c    = tid - item * 3;
            psm[item * PPAD + c] = rp[tid];
        }
    }
    __syncthreads();

    // ------- Phase 2: FK chain, threads 0..31 ------------------------------
    // Rot chain in registers (critical path); positions staged to smem and
    // parent positions re-read from smem (keeps live regs <= 85 for 6 CTAs).
    if (tid < ITEMS) {
        float* my = rsm + tid * RPAD;        // this item's 24 rot slots
        float* mp = psm + tid * PPAD;        // this item's 24 pos slots

        float G[NJ][9];                      // SSA'd by full unroll; ~3 live

#pragma unroll
        for (int c = 0; c < 9; ++c) G[0][c] = my[c];    // joint 0: G == L
        // mp[0..2] already holds the root position (staged in phase 1).

#pragma unroll
        for (int j = 1; j < NJ; ++j) {
            const int p = par_of(j);

            float L[9];
#pragma unroll
            for (int c = 0; c < 9; ++c) L[c] = my[j * 9 + c];

            const float o0 = soffs[j * 3 + 0];
            const float o1 = soffs[j * 3 + 1];
            const float o2 = soffs[j * 3 + 2];

            // position: parent pos re-read from smem (same-thread RAW, safe)
#pragma unroll
            for (int i = 0; i < 3; ++i) {
                mp[j * 3 + i] = mp[p * 3 + i]
                              + G[p][i * 3 + 0] * o0
                              + G[p][i * 3 + 1] * o1
                              + G[p][i * 3 + 2] * o2;
            }
            // rotation: G[j] = G[p] @ L[j], staged in place over L[j]
#pragma unroll
            for (int i = 0; i < 3; ++i) {
#pragma unroll
                for (int c = 0; c < 3; ++c) {
                    float g = G[p][i * 3 + 0] * L[0 * 3 + c]
                            + G[p][i * 3 + 1] * L[1 * 3 + c]
                            + G[p][i * 3 + 2] * L[2 * 3 + c];
                    G[j][i * 3 + c] = g;
                    my[j * 9 + i * 3 + c] = g;
                }
            }
        }
    }
    __syncthreads();

    // ------- Phase 3: coalesced smem -> gmem (global rots, then pos) -------
    {
        const long long rot_base = base_item * 216;
#pragma unroll
        for (int k = 0; k < (ITEMS * 216) / TPB; ++k) {   // 54 iterations
            int idx  = k * TPB + tid;
            int item = idx / 216;
            int e    = idx - item * 216;
            out_rot[rot_base + idx] = rsm[item * RPAD + e];
        }
        const long long pos_base = base_item * 72;
#pragma unroll
        for (int k = 0; k < (ITEMS * 72) / TPB; ++k) {    // 18 iterations
            int idx  = k * TPB + tid;
            int item = idx / 72;
            int e    = idx - item * 72;
            out_pos[pos_base + idx] = psm[item * PPAD + e];
        }
    }
}

extern "C" void kernel_launch(void* const* d_in, const int* in_sizes, int n_in,
                              void* d_out, int out_size)
{
    const float* lrots = (const float*)d_in[0];
    const float* rootp = (const float*)d_in[1];
    const float* offs  = (const float*)d_in[2];
    float*       out   = (float*)d_out;

    const int batch = in_sizes[0] / 216;                 // 262144
    const int grid  = batch / ITEMS;                     // 8192 blocks
    const int smem  = (ITEMS * RPAD + ITEMS * PPAD) * (int)sizeof(float); // 37,120 B

    cudaFuncSetAttribute(fk_kernel,
                         cudaFuncAttributeMaxDynamicSharedMemorySize, smem);

    fk_kernel<<<grid, TPB, smem>>>(lrots, rootp, offs, out, batch);
}